// round 11
// baseline (speedup 1.0000x reference)
#include <cuda_runtime.h>
#include <cuda_fp16.h>
#include <cstdint>

// CompressionLayer grouped GEMM via mma.sync fp16 (f32 accumulate).
// y[b,n,o] = relu( sum_k x[b,n,k] * Wk[n,o,k] + bk[n,o] )
// Persistent-style CTAs with dynamic chunk scheduling (atomic counter,
// reset by a prologue kernel) to kill wave-tail quantization.
// Per chunk n: D[256,64] = X[256,256]*W[64,256]^T as two 128-batch halves
// sharing one W load; X pipelined in 16 k-stages of 32, 2-stage LDG cover.

#define NTHREADS 256
#define BT 128
#define NCHUNKS 1024

// smem layout
#define S_W     0        // 64 rows x 512B (256 fp16), swizzled
#define S_X0    32768    // stage buf 0: 128 rows x 128B (k=32 fp16 + pad)
#define S_X1    49152    // stage buf 1
#define S_BIAS  65536    // 64 f32
#define S_CTR   65792    // broadcast slot for chunk id
#define S_TOTAL 65808

__device__ unsigned int g_work_ctr;

__global__ void reset_ctr_kernel() { g_work_ctr = 0u; }

static __device__ __forceinline__ uint32_t smem_u32(const void* p) {
    uint32_t a;
    asm("{ .reg .u64 t; cvta.to.shared.u64 t, %1; cvt.u32.u64 %0, t; }"
        : "=r"(a) : "l"(p));
    return a;
}

static __device__ __forceinline__ void ldmatrix_x4(uint32_t& a0, uint32_t& a1,
                                                   uint32_t& a2, uint32_t& a3,
                                                   uint32_t addr) {
    asm volatile("ldmatrix.sync.aligned.m8n8.x4.shared.b16 {%0,%1,%2,%3}, [%4];"
                 : "=r"(a0), "=r"(a1), "=r"(a2), "=r"(a3) : "r"(addr));
}

static __device__ __forceinline__ void mma16816(float* c, uint32_t a0, uint32_t a1,
                                                uint32_t a2, uint32_t a3,
                                                uint32_t b0, uint32_t b1) {
    asm volatile(
        "mma.sync.aligned.m16n8k16.row.col.f32.f16.f16.f32 "
        "{%0,%1,%2,%3}, {%4,%5,%6,%7}, {%8,%9}, {%0,%1,%2,%3};"
        : "+f"(c[0]), "+f"(c[1]), "+f"(c[2]), "+f"(c[3])
        : "r"(a0), "r"(a1), "r"(a2), "r"(a3), "r"(b0), "r"(b1));
}

// f32x4 -> fp16x4, 8B store into swizzled row of given byte stride
template <int STRIDE>
static __device__ __forceinline__ void cvt_store(char* dst, int row, int kcol,
                                                 float4 v) {
    __half2 h01 = __floats2half2_rn(v.x, v.y);
    __half2 h23 = __floats2half2_rn(v.z, v.w);
    int phys = row * STRIDE + ((kcol * 2) ^ ((row & 7) << 4));
    *reinterpret_cast<uint2*>(dst + phys) =
        make_uint2(*(uint32_t*)&h01, *(uint32_t*)&h23);
}

__global__ void __launch_bounds__(NTHREADS, 2)
compression_mma_kernel(const float* __restrict__ xg,
                       const float* __restrict__ Wg,
                       const float* __restrict__ bkg,
                       float* __restrict__ out) {
    extern __shared__ char sm[];
    const uint32_t sb = smem_u32(sm);
    const int tid = threadIdx.x;
    const int wid = tid >> 5;
    const int lid = tid & 31;

    // ---- per-thread constants (chunk-independent) ----
    const int ld_b  = wid * 4 + (lid >> 3);      // loader base batch
    const int ld_ri = (lid >> 2) & 1;
    const int ld_j  = (lid & 3) << 2;
    const int sts_k = ld_ri * 16 + ld_j;

    const int wm  = (wid & 3) << 5;
    const int wn  = (wid >> 2) << 5;

    const int ar0 = wm + (lid & 15);
    const int ar1 = ar0 + 16;
    const uint32_t a0_base = ar0 * 128;
    const uint32_t a1_base = ar1 * 128;
    const uint32_t a0_sw   = (uint32_t)(ar0 & 7) << 4;
    const uint32_t a1_sw   = (uint32_t)(ar1 & 7) << 4;
    const uint32_t a_coff  = (uint32_t)(lid >> 4) << 4;

    const int bn0 = wn + ((lid >> 4) << 3) + (lid & 7);
    const int bn1 = bn0 + 16;
    const uint32_t b0_base = sb + S_W + bn0 * 512;
    const uint32_t b1_base = sb + S_W + bn1 * 512;
    const uint32_t b0_sw   = (uint32_t)(bn0 & 7) << 4;
    const uint32_t b1_sw   = (uint32_t)(bn1 & 7) << 4;
    const uint32_t b_coff  = (uint32_t)((lid >> 3) & 1) << 4;

    const int g = lid >> 2;
    const int t = lid & 3;

    #define X_LDG(regs, st)                                                   \
        {                                                                     \
            const float* p0 = xbase +                                         \
                (size_t)(((st) >> 3) * BT + ld_b) * 262144 +                  \
                (((st) & 7) * 2 + ld_ri) * 512 + ld_j;                        \
            _Pragma("unroll")                                                 \
            for (int il = 0; il < 4; ++il)                                    \
                regs[il] = *reinterpret_cast<const float4*>(                  \
                    p0 + (size_t)il * 32 * 262144);                           \
        }

    #define X_STS(regs, buf)                                                  \
        {                                                                     \
            char* dst = sm + ((buf) ? S_X1 : S_X0);                           \
            _Pragma("unroll")                                                 \
            for (int il = 0; il < 4; ++il)                                    \
                cvt_store<128>(dst, ld_b + il * 32, sts_k, regs[il]);         \
        }

    // ---- dynamic chunk loop ----
    for (;;) {
        if (tid == 0)
            *reinterpret_cast<unsigned*>(sm + S_CTR) = atomicAdd(&g_work_ctr, 1u);
        __syncthreads();   // also protects smem reuse from previous chunk
        const unsigned n = *reinterpret_cast<unsigned*>(sm + S_CTR);
        if (n >= NCHUNKS) break;

        const int ch = n >> 5;
        const int cw = n & 31;
        const float* xbase = xg + (size_t)(ch * 16) * 512 + cw * 16;

        // stage-0 X LDG hoisted above W prologue for latency cover
        float4 r0[4], r1[4];
        X_LDG(r0, 0);

        // ---- W[n] 64x256 f32 -> fp16 smem (once per chunk), bias ----
        {
            const float4* Wg4 =
                reinterpret_cast<const float4*>(Wg + (size_t)n * 64 * 256);
            #pragma unroll
            for (int it = 0; it < 16; ++it) {
                int e  = tid + it * NTHREADS;
                int o  = e >> 6;
                int k4 = (e & 63) << 2;
                cvt_store<512>(sm + S_W, o, k4, Wg4[e]);
            }
        }
        if (tid < 64)
            reinterpret_cast<float*>(sm + S_BIAS)[tid] = bkg[n * 64 + tid];

        X_STS(r0, 0);
        X_LDG(r1, 1);
        __syncthreads();

        float acc[2][4][4];
        #pragma unroll
        for (int i = 0; i < 2; ++i)
            #pragma unroll
            for (int j = 0; j < 4; ++j)
                #pragma unroll
                for (int e = 0; e < 4; ++e) acc[i][j][e] = 0.f;

        auto compute_stage = [&](uint32_t xb, int s8) {
            #pragma unroll
            for (int sl = 0; sl < 2; ++sl) {
                const uint32_t colA = ((uint32_t)sl << 5) | a_coff;
                uint32_t x00, x01, x02, x03, x10, x11, x12, x13;
                ldmatrix_x4(x00, x01, x02, x03, xb + a0_base + (colA ^ a0_sw));
                ldmatrix_x4(x10, x11, x12, x13, xb + a1_base + (colA ^ a1_sw));

                const uint32_t colB = ((uint32_t)(s8 * 2 + sl) << 5) | b_coff;
                uint32_t u0, u1, u2, u3, v0, v1, v2, v3;
                ldmatrix_x4(u0, u1, u2, u3, b0_base + (colB ^ b0_sw));
                ldmatrix_x4(v0, v1, v2, v3, b1_base + (colB ^ b1_sw));

                mma16816(acc[0][0], x00, x01, x02, x03, u0, u1);
                mma16816(acc[0][1], x00, x01, x02, x03, u2, u3);
                mma16816(acc[0][2], x00, x01, x02, x03, v0, v1);
                mma16816(acc[0][3], x00, x01, x02, x03, v2, v3);
                mma16816(acc[1][0], x10, x11, x12, x13, u0, u1);
                mma16816(acc[1][1], x10, x11, x12, x13, u2, u3);
                mma16816(acc[1][2], x10, x11, x12, x13, v0, v1);
                mma16816(acc[1][3], x10, x11, x12, x13, v2, v3);
            }
        };

        auto epilogue = [&](int bt) {
            const float* Bs = reinterpret_cast<const float*>(sm + S_BIAS);
            #pragma unroll
            for (int mt = 0; mt < 2; ++mt) {
                #pragma unroll
                for (int nt = 0; nt < 4; ++nt) {
                    int ob  = wn + nt * 8;
                    int oi  = ob >> 3;
                    int oj  = 2 * t;
                    float bi0 = Bs[ob + oj];
                    float bi1 = Bs[ob + oj + 1];

                    size_t colofs = (size_t)(ch * 8 + oi) * 256 + cw * 8 + oj;
                    int bg0 = bt * BT + wm + mt * 16 + g;
                    float2 w0 = make_float2(fmaxf(acc[mt][nt][0] + bi0, 0.f),
                                            fmaxf(acc[mt][nt][1] + bi1, 0.f));
                    *reinterpret_cast<float2*>(out + (size_t)bg0 * 65536 + colofs) = w0;

                    int bg1 = bg0 + 8;
                    float2 w1 = make_float2(fmaxf(acc[mt][nt][2] + bi0, 0.f),
                                            fmaxf(acc[mt][nt][3] + bi1, 0.f));
                    *reinterpret_cast<float2*>(out + (size_t)bg1 * 65536 + colofs) = w1;
                }
            }
        };

        // ---- 16-stage pipeline, two-stage LDG latency cover ----
        #pragma unroll
        for (int st = 0; st < 16; ++st) {
            if (st < 14) {
                if (st & 1) { X_LDG(r1, st + 2); }
                else        { X_LDG(r0, st + 2); }
            }

            compute_stage(sb + ((st & 1) ? S_X1 : S_X0), st & 7);

            if (st < 15) {
                if ((st + 1) & 1) { X_STS(r1, 1); }
                else              { X_STS(r0, 0); }
                __syncthreads();
            }

            if (st == 7) {
                epilogue(0);
                #pragma unroll
                for (int i = 0; i < 2; ++i)
                    #pragma unroll
                    for (int j = 0; j < 4; ++j)
                        #pragma unroll
                        for (int e = 0; e < 4; ++e) acc[i][j][e] = 0.f;
            }
        }
        epilogue(1);
    }

    #undef X_LDG
    #undef X_STS
}

extern "C" void kernel_launch(void* const* d_in, const int* in_sizes, int n_in,
                              void* d_out, int out_size) {
    const float* x  = (const float*)d_in[0];   // [256,512,512]
    const float* Wk = (const float*)d_in[1];   // [1024,64,256]
    const float* bk = (const float*)d_in[2];   // [1024,64]
    float* out = (float*)d_out;                // [256, 65536]

    cudaFuncSetAttribute(compression_mma_kernel,
                         cudaFuncAttributeMaxDynamicSharedMemorySize, S_TOTAL);

    reset_ctr_kernel<<<1, 1>>>();
    compression_mma_kernel<<<NCHUNKS, NTHREADS, S_TOTAL>>>(x, Wk, bk, out);
}